// round 6
// baseline (speedup 1.0000x reference)
#include <cuda_runtime.h>
#include <cuda_bf16.h>
#include <math.h>

// Problem constants
#define NMAX 50000
#define EMAX 800000
#define HDIM 128
#define GCNT 128
#define CCNT 10
#define SCAN_BLK 512

// ---------------- device scratch (no cudaMalloc allowed) ----------------
__device__ float g_h[NMAX * HDIM];
__device__ float g_agg[NMAX * HDIM];
__device__ float g_h3[NMAX * 16];
__device__ float g_deg[NMAX];
__device__ float g_dinv[NMAX];
__device__ int   g_cnt[NMAX];
__device__ int   g_row[NMAX + 1];
__device__ int   g_cur[NMAX];
__device__ int   g_bsum[128];
__device__ int   g_boff[128];
__device__ int   g_esrc[EMAX];
__device__ float g_ew2[EMAX];
__device__ float g_psum[GCNT * CCNT];
__device__ float g_pcnt[GCNT];

// ---------------- preprocessing ----------------

__global__ void k_init(int n) {
    int i = blockIdx.x * blockDim.x + threadIdx.x;
    if (i < n) { g_deg[i] = 1.0f; g_cnt[i] = 0; }
    if (i < GCNT * CCNT) g_psum[i] = 0.0f;
    if (i < GCNT) g_pcnt[i] = 0.0f;
}

__global__ void k_count(const int* __restrict__ dst, const float* __restrict__ ew, int e) {
    int i = blockIdx.x * blockDim.x + threadIdx.x;
    if (i >= e) return;
    int d = dst[i];
    atomicAdd(&g_deg[d], ew[i]);
    atomicAdd(&g_cnt[d], 1);
}

__global__ void k_scan1(int n) {
    __shared__ int sd[SCAN_BLK];
    int tid = threadIdx.x;
    int i = blockIdx.x * SCAN_BLK + tid;
    int v = (i < n) ? g_cnt[i] : 0;
    sd[tid] = v;
    __syncthreads();
#pragma unroll
    for (int off = 1; off < SCAN_BLK; off <<= 1) {
        int t = (tid >= off) ? sd[tid - off] : 0;
        __syncthreads();
        sd[tid] += t;
        __syncthreads();
    }
    if (i < n) g_row[i] = sd[tid] - v;
    if (tid == SCAN_BLK - 1) g_bsum[blockIdx.x] = sd[SCAN_BLK - 1];
}

__global__ void k_scan2(int nb, int n, int e) {
    __shared__ int sd[128];
    int tid = threadIdx.x;
    int v = (tid < nb) ? g_bsum[tid] : 0;
    sd[tid] = v;
    __syncthreads();
#pragma unroll
    for (int off = 1; off < 128; off <<= 1) {
        int t = (tid >= off) ? sd[tid - off] : 0;
        __syncthreads();
        sd[tid] += t;
        __syncthreads();
    }
    if (tid < nb) g_boff[tid] = sd[tid] - v;
    if (tid == 0) g_row[n] = e;
}

__global__ void k_scan3(int n) {
    int i = blockIdx.x * SCAN_BLK + threadIdx.x;
    if (i < n) {
        int r = g_row[i] + g_boff[blockIdx.x];
        g_row[i] = r;
        g_cur[i] = r;
        float d = g_deg[i];
        g_dinv[i] = (d > 0.0f) ? rsqrtf(d) : 0.0f;
    }
}

__global__ void k_scatter(const int* __restrict__ src, const int* __restrict__ dst,
                          const float* __restrict__ ew, int e) {
    int i = blockIdx.x * blockDim.x + threadIdx.x;
    if (i >= e) return;
    int s = src[i], d = dst[i];
    int pos = atomicAdd(&g_cur[d], 1);
    g_esrc[pos] = s;
    g_ew2[pos] = ew[i] * g_dinv[s];
}

// ---------------- tensor-core GEMM (3xTF32, split-at-load, double-buffered) ----
// [M,128] @ [128,128] -> [M,128]; BM=128 BN=128 BK=16; 256 threads = 8 warps.
// Operands pre-split into (hi,lo) float2 in smem; inner loop = LDS.64 + HMMA only.
#define TF32_MASK 0xFFFFE000u
#define A_STRIDE 20
#define B_STRIDE 136
#define AS_ELEMS (128 * A_STRIDE)          // per buffer, float2
#define BS_ELEMS (16 * B_STRIDE)
#define GEMM_SMEM_BYTES ((2 * (AS_ELEMS + BS_ELEMS)) * (int)sizeof(float2))  // 75776

__device__ __forceinline__ void mma_tf32(float* c, const unsigned* a,
                                         unsigned b0, unsigned b1) {
    asm volatile(
        "mma.sync.aligned.m16n8k8.row.col.f32.tf32.tf32.f32 "
        "{%0,%1,%2,%3}, {%4,%5,%6,%7}, {%8,%9}, {%0,%1,%2,%3};\n"
        : "+f"(c[0]), "+f"(c[1]), "+f"(c[2]), "+f"(c[3])
        : "r"(a[0]), "r"(a[1]), "r"(a[2]), "r"(a[3]), "r"(b0), "r"(b1));
}

__device__ __forceinline__ float2 split_f32(float v) {
    unsigned hb = __float_as_uint(v) & TF32_MASK;
    float hf = __uint_as_float(hb);
    return make_float2(hf, v - hf);
}

__global__ __launch_bounds__(256, 2)
void sgemm128_tf32(const float* __restrict__ A, const float* __restrict__ B,
                   float* __restrict__ C, int M) {
    extern __shared__ float2 sm[];
    float2* As = sm;                         // [2][128][A_STRIDE]
    float2* Bs = sm + 2 * AS_ELEMS;          // [2][16][B_STRIDE]

    int tid  = threadIdx.x;
    int warp = tid >> 5;
    int lane = tid & 31;
    int g = lane >> 2;      // 0..7
    int t = lane & 3;       // 0..3
    int r0 = warp * 16;
    int rowBase = blockIdx.x * 128;

    int aRow = tid >> 1;          // 0..127
    int aOff = (tid & 1) * 8;     // 0 or 8
    int bRow = tid >> 4;          // 0..15
    int bOff = (tid & 15) * 8;    // 0..120

    bool aOk = (rowBase + aRow) < M;
    const float* Ap = A + (size_t)(aOk ? rowBase + aRow : 0) * 128;

    float acc[16][4];
#pragma unroll
    for (int j = 0; j < 16; j++)
#pragma unroll
        for (int q = 0; q < 4; q++) acc[j][q] = 0.0f;

    // prefetch tile 0 into registers and store split into buffer 0
    {
        float4 z = make_float4(0.f, 0.f, 0.f, 0.f);
        float4 ra0 = aOk ? *(const float4*)(Ap + aOff)     : z;
        float4 ra1 = aOk ? *(const float4*)(Ap + aOff + 4) : z;
        float4 rb0 = *(const float4*)(B + (size_t)bRow * 128 + bOff);
        float4 rb1 = *(const float4*)(B + (size_t)bRow * 128 + bOff + 4);
        float av[8] = {ra0.x, ra0.y, ra0.z, ra0.w, ra1.x, ra1.y, ra1.z, ra1.w};
        float bv[8] = {rb0.x, rb0.y, rb0.z, rb0.w, rb1.x, rb1.y, rb1.z, rb1.w};
#pragma unroll
        for (int q = 0; q < 8; q++) As[aRow * A_STRIDE + aOff + q] = split_f32(av[q]);
#pragma unroll
        for (int q = 0; q < 8; q++) Bs[bRow * B_STRIDE + bOff + q] = split_f32(bv[q]);
    }
    __syncthreads();

    int p = 0;
    for (int k0 = 0; k0 < 128; k0 += 16) {
        bool more = (k0 + 16) < 128;
        float4 ra0, ra1, rb0, rb1;
        if (more) {
            float4 z = make_float4(0.f, 0.f, 0.f, 0.f);
            ra0 = aOk ? *(const float4*)(Ap + k0 + 16 + aOff)     : z;
            ra1 = aOk ? *(const float4*)(Ap + k0 + 16 + aOff + 4) : z;
            rb0 = *(const float4*)(B + (size_t)(k0 + 16 + bRow) * 128 + bOff);
            rb1 = *(const float4*)(B + (size_t)(k0 + 16 + bRow) * 128 + bOff + 4);
        }

        const float2* Ab = As + p * AS_ELEMS;
        const float2* Bb = Bs + p * BS_ELEMS;
#pragma unroll
        for (int kk = 0; kk < 16; kk += 8) {
            float2 a0 = Ab[(r0 + g    ) * A_STRIDE + kk + t];
            float2 a1 = Ab[(r0 + g + 8) * A_STRIDE + kk + t];
            float2 a2 = Ab[(r0 + g    ) * A_STRIDE + kk + t + 4];
            float2 a3 = Ab[(r0 + g + 8) * A_STRIDE + kk + t + 4];
            unsigned ahi[4] = {__float_as_uint(a0.x), __float_as_uint(a1.x),
                               __float_as_uint(a2.x), __float_as_uint(a3.x)};
            unsigned alo[4] = {__float_as_uint(a0.y), __float_as_uint(a1.y),
                               __float_as_uint(a2.y), __float_as_uint(a3.y)};
#pragma unroll
            for (int j = 0; j < 16; j++) {
                float2 b0 = Bb[(kk + t    ) * B_STRIDE + j * 8 + g];
                float2 b1 = Bb[(kk + t + 4) * B_STRIDE + j * 8 + g];
                mma_tf32(acc[j], ahi, __float_as_uint(b0.x), __float_as_uint(b1.x)); // hi*hi
                mma_tf32(acc[j], ahi, __float_as_uint(b0.y), __float_as_uint(b1.y)); // hi*lo
                mma_tf32(acc[j], alo, __float_as_uint(b0.x), __float_as_uint(b1.x)); // lo*hi
            }
        }

        if (more) {
            // store next tile into the other buffer (not currently read by anyone)
            int q = p ^ 1;
            float2* Aq = As + q * AS_ELEMS;
            float2* Bq = Bs + q * BS_ELEMS;
            float av[8] = {ra0.x, ra0.y, ra0.z, ra0.w, ra1.x, ra1.y, ra1.z, ra1.w};
            float bv[8] = {rb0.x, rb0.y, rb0.z, rb0.w, rb1.x, rb1.y, rb1.z, rb1.w};
#pragma unroll
            for (int qq = 0; qq < 8; qq++) Aq[aRow * A_STRIDE + aOff + qq] = split_f32(av[qq]);
#pragma unroll
            for (int qq = 0; qq < 8; qq++) Bq[bRow * B_STRIDE + bOff + qq] = split_f32(bv[qq]);
            __syncthreads();
            p = q;
        }
    }

    int rA = rowBase + r0 + g;
    int rB = rA + 8;
#pragma unroll
    for (int j = 0; j < 16; j++) {
        int col = j * 8 + 2 * t;
        if (rA < M) *(float2*)(C + (size_t)rA * 128 + col) = make_float2(acc[j][0], acc[j][1]);
        if (rB < M) *(float2*)(C + (size_t)rB * 128 + col) = make_float2(acc[j][2], acc[j][3]);
    }
}

// ---------------- aggregation ----------------
__global__ __launch_bounds__(256)
void agg_h128(const float* __restrict__ h, float* __restrict__ out,
              const float* __restrict__ bias, int do_relu, int n) {
    int gw = (blockIdx.x * blockDim.x + threadIdx.x) >> 5;
    if (gw >= n) return;
    int lane = threadIdx.x & 31;
    const float4* h4 = (const float4*)h;

    float di = g_dinv[gw];
    float4 acc = h4[gw * 32 + lane];
    acc.x *= di; acc.y *= di; acc.z *= di; acc.w *= di;

    int j = g_row[gw];
    int end = g_row[gw + 1];
    for (; j + 4 <= end; j += 4) {
        int s0 = g_esrc[j], s1 = g_esrc[j + 1], s2 = g_esrc[j + 2], s3 = g_esrc[j + 3];
        float w0 = g_ew2[j], w1 = g_ew2[j + 1], w2 = g_ew2[j + 2], w3 = g_ew2[j + 3];
        float4 v0 = h4[s0 * 32 + lane];
        float4 v1 = h4[s1 * 32 + lane];
        float4 v2 = h4[s2 * 32 + lane];
        float4 v3 = h4[s3 * 32 + lane];
        acc.x = fmaf(w0, v0.x, acc.x); acc.y = fmaf(w0, v0.y, acc.y);
        acc.z = fmaf(w0, v0.z, acc.z); acc.w = fmaf(w0, v0.w, acc.w);
        acc.x = fmaf(w1, v1.x, acc.x); acc.y = fmaf(w1, v1.y, acc.y);
        acc.z = fmaf(w1, v1.z, acc.z); acc.w = fmaf(w1, v1.w, acc.w);
        acc.x = fmaf(w2, v2.x, acc.x); acc.y = fmaf(w2, v2.y, acc.y);
        acc.z = fmaf(w2, v2.z, acc.z); acc.w = fmaf(w2, v2.w, acc.w);
        acc.x = fmaf(w3, v3.x, acc.x); acc.y = fmaf(w3, v3.y, acc.y);
        acc.z = fmaf(w3, v3.z, acc.z); acc.w = fmaf(w3, v3.w, acc.w);
    }
    for (; j < end; j++) {
        int s = g_esrc[j];
        float w = g_ew2[j];
        float4 v = h4[s * 32 + lane];
        acc.x = fmaf(w, v.x, acc.x); acc.y = fmaf(w, v.y, acc.y);
        acc.z = fmaf(w, v.z, acc.z); acc.w = fmaf(w, v.w, acc.w);
    }

    float4 bb = ((const float4*)bias)[lane];
    acc.x = fmaf(acc.x, di, bb.x);
    acc.y = fmaf(acc.y, di, bb.y);
    acc.z = fmaf(acc.z, di, bb.z);
    acc.w = fmaf(acc.w, di, bb.w);
    if (do_relu) {
        acc.x = fmaxf(acc.x, 0.f); acc.y = fmaxf(acc.y, 0.f);
        acc.z = fmaxf(acc.z, 0.f); acc.w = fmaxf(acc.w, 0.f);
    }
    ((float4*)out)[gw * 32 + lane] = acc;
}

// ---------------- layer 3 projection ----------------
__global__ __launch_bounds__(512)
void gemm_w3(const float* __restrict__ A, const float* __restrict__ W, int M) {
    __shared__ float xs[32][128];
    __shared__ float Ws[128 * CCNT];
    int tid = threadIdx.x;
    int r0 = blockIdx.x * 32;

    for (int t = tid; t < 1024; t += 512) {
        int r = t >> 5;
        int c4 = (t & 31) << 2;
        int grow = r0 + r;
        float4 v = make_float4(0.f, 0.f, 0.f, 0.f);
        if (grow < M) v = *(const float4*)(A + (size_t)grow * 128 + c4);
        *(float4*)&xs[r][c4] = v;
    }
    for (int t = tid; t < 128 * CCNT; t += 512) Ws[t] = W[t];
    __syncthreads();

    int r = tid >> 4;
    int c = tid & 15;
    if (c < CCNT) {
        float acc = 0.0f;
#pragma unroll
        for (int k = 0; k < 128; k++)
            acc = fmaf(xs[r][k], Ws[k * CCNT + c], acc);
        int grow = r0 + r;
        if (grow < M) g_h3[grow * 16 + c] = acc;
    }
}

// ---------------- layer 3 aggregation + pool ----------------
__global__ __launch_bounds__(256)
void agg_c16_pool(const int* __restrict__ batch, const float* __restrict__ b3, int n) {
    int gw = (blockIdx.x * blockDim.x + threadIdx.x) >> 5;
    if (gw >= n) return;
    int lane = threadIdx.x & 31;
    bool active = (lane < CCNT);

    float di = g_dinv[gw];
    float acc = 0.0f;
    if (active) acc = g_h3[gw * 16 + lane] * di;

    int j = g_row[gw];
    int end = g_row[gw + 1];
    for (; j + 4 <= end; j += 4) {
        int s0 = g_esrc[j], s1 = g_esrc[j + 1], s2 = g_esrc[j + 2], s3 = g_esrc[j + 3];
        float w0 = g_ew2[j], w1 = g_ew2[j + 1], w2 = g_ew2[j + 2], w3 = g_ew2[j + 3];
        if (active) {
            acc = fmaf(w0, g_h3[s0 * 16 + lane], acc);
            acc = fmaf(w1, g_h3[s1 * 16 + lane], acc);
            acc = fmaf(w2, g_h3[s2 * 16 + lane], acc);
            acc = fmaf(w3, g_h3[s3 * 16 + lane], acc);
        }
    }
    for (; j < end; j++) {
        int s = g_esrc[j];
        float w = g_ew2[j];
        if (active) acc = fmaf(w, g_h3[s * 16 + lane], acc);
    }

    int g = batch[gw];
    if (active) {
        acc = fmaf(acc, di, b3[lane]);
        atomicAdd(&g_psum[g * CCNT + lane], acc);
    }
    if (lane == 0) atomicAdd(&g_pcnt[g], 1.0f);
}

// ---------------- final: mean + log_softmax ----------------
__global__ void k_finalize(float* __restrict__ out) {
    int g = threadIdx.x;
    if (g >= GCNT) return;
    float c = fmaxf(g_pcnt[g], 1.0f);
    float v[CCNT];
    float m = -1e30f;
#pragma unroll
    for (int j = 0; j < CCNT; j++) {
        v[j] = g_psum[g * CCNT + j] / c;
        m = fmaxf(m, v[j]);
    }
    float s = 0.0f;
#pragma unroll
    for (int j = 0; j < CCNT; j++) s += expf(v[j] - m);
    float lse = logf(s) + m;
#pragma unroll
    for (int j = 0; j < CCNT; j++) out[g * CCNT + j] = v[j] - lse;
}

// ---------------- launch ----------------
extern "C" void kernel_launch(void* const* d_in, const int* in_sizes, int n_in,
                              void* d_out, int out_size) {
    const float* x    = (const float*)d_in[0];
    const int*   ei   = (const int*)d_in[1];
    const float* ea   = (const float*)d_in[2];
    const int*   bat  = (const int*)d_in[3];
    const float* W1   = (const float*)d_in[4];
    const float* b1   = (const float*)d_in[5];
    const float* W2   = (const float*)d_in[6];
    const float* b2   = (const float*)d_in[7];
    const float* W3   = (const float*)d_in[8];
    const float* b3   = (const float*)d_in[9];
    float* out = (float*)d_out;

    int n = in_sizes[0] / HDIM;   // 50000
    int e = in_sizes[1] / 2;      // 800000
    const int* src = ei;
    const int* dst = ei + e;

    float *gh, *gagg;
    cudaGetSymbolAddress((void**)&gh, g_h);
    cudaGetSymbolAddress((void**)&gagg, g_agg);

    // allow >48KB dynamic smem for the GEMM (idempotent, host-side, capture-legal)
    cudaFuncSetAttribute(sgemm128_tf32,
                         cudaFuncAttributeMaxDynamicSharedMemorySize, GEMM_SMEM_BYTES);

    int nb = (n + SCAN_BLK - 1) / SCAN_BLK;
    int gemmBlocks = (n + 127) / 128;
    int aggBlocks = (n * 32 + 255) / 256;

    // --- preprocessing: degrees + CSR-by-dst ---
    k_init<<<(n + 255) / 256, 256>>>(n);
    k_count<<<(e + 255) / 256, 256>>>(dst, ea, e);
    k_scan1<<<nb, SCAN_BLK>>>(n);
    k_scan2<<<1, 128>>>(nb, n, e);
    k_scan3<<<nb, SCAN_BLK>>>(n);
    k_scatter<<<(e + 255) / 256, 256>>>(src, dst, ea, e);

    // layer 1
    sgemm128_tf32<<<gemmBlocks, 256, GEMM_SMEM_BYTES>>>(x, W1, gh, n);
    agg_h128<<<aggBlocks, 256>>>(gh, gagg, b1, 1, n);

    // layer 2
    sgemm128_tf32<<<gemmBlocks, 256, GEMM_SMEM_BYTES>>>(gagg, W2, gh, n);
    agg_h128<<<aggBlocks, 256>>>(gh, gagg, b2, 1, n);

    // layer 3: project to C first, then aggregate + pool
    gemm_w3<<<(n + 31) / 32, 512>>>(gagg, W3, n);
    agg_c16_pool<<<aggBlocks, 256>>>(bat, b3, n);

    k_finalize<<<1, 128>>>(out);
}

// round 7
// speedup vs baseline: 1.1977x; 1.1977x over previous
#include <cuda_runtime.h>
#include <cuda_bf16.h>
#include <math.h>

// Problem constants
#define NMAX 50000
#define EMAX 800000
#define HDIM 128
#define GCNT 128
#define CCNT 10
#define SCAN_BLK 512

// ---------------- device scratch (no cudaMalloc allowed) ----------------
__device__ float g_h[NMAX * HDIM];
__device__ float g_agg[NMAX * HDIM];
__device__ float g_h3[NMAX * 16];
__device__ float g_deg[NMAX];
__device__ float g_dinv[NMAX];
__device__ int   g_cnt[NMAX];
__device__ int   g_row[NMAX + 1];
__device__ int   g_cur[NMAX];
__device__ int   g_bsum[128];
__device__ int   g_boff[128];
__device__ int   g_esrc[EMAX];
__device__ float g_ew2[EMAX];
__device__ float g_psum[GCNT * CCNT];
__device__ float g_pcnt[GCNT];

// ---------------- preprocessing ----------------

__global__ void k_init(int n) {
    int i = blockIdx.x * blockDim.x + threadIdx.x;
    if (i < n) { g_deg[i] = 1.0f; g_cnt[i] = 0; }
    if (i < GCNT * CCNT) g_psum[i] = 0.0f;
    if (i < GCNT) g_pcnt[i] = 0.0f;
}

__global__ void k_count(const int* __restrict__ dst, const float* __restrict__ ew, int e) {
    int i = blockIdx.x * blockDim.x + threadIdx.x;
    if (i >= e) return;
    int d = dst[i];
    atomicAdd(&g_deg[d], ew[i]);
    atomicAdd(&g_cnt[d], 1);
}

__global__ void k_scan1(int n) {
    __shared__ int sd[SCAN_BLK];
    int tid = threadIdx.x;
    int i = blockIdx.x * SCAN_BLK + tid;
    int v = (i < n) ? g_cnt[i] : 0;
    sd[tid] = v;
    __syncthreads();
#pragma unroll
    for (int off = 1; off < SCAN_BLK; off <<= 1) {
        int t = (tid >= off) ? sd[tid - off] : 0;
        __syncthreads();
        sd[tid] += t;
        __syncthreads();
    }
    if (i < n) g_row[i] = sd[tid] - v;
    if (tid == SCAN_BLK - 1) g_bsum[blockIdx.x] = sd[SCAN_BLK - 1];
}

__global__ void k_scan2(int nb, int n, int e) {
    __shared__ int sd[128];
    int tid = threadIdx.x;
    int v = (tid < nb) ? g_bsum[tid] : 0;
    sd[tid] = v;
    __syncthreads();
#pragma unroll
    for (int off = 1; off < 128; off <<= 1) {
        int t = (tid >= off) ? sd[tid - off] : 0;
        __syncthreads();
        sd[tid] += t;
        __syncthreads();
    }
    if (tid < nb) g_boff[tid] = sd[tid] - v;
    if (tid == 0) g_row[n] = e;
}

// phase 3 + dinv fused
__global__ void k_scan3(int n) {
    int i = blockIdx.x * SCAN_BLK + threadIdx.x;
    if (i < n) {
        int r = g_row[i] + g_boff[blockIdx.x];
        g_row[i] = r;
        g_cur[i] = r;
        float d = g_deg[i];
        g_dinv[i] = (d > 0.0f) ? rsqrtf(d) : 0.0f;
    }
}

__global__ void k_scatter(const int* __restrict__ src, const int* __restrict__ dst,
                          const float* __restrict__ ew, int e) {
    int i = blockIdx.x * blockDim.x + threadIdx.x;
    if (i >= e) return;
    int s = src[i], d = dst[i];
    int pos = atomicAdd(&g_cur[d], 1);
    g_esrc[pos] = s;
    g_ew2[pos] = ew[i] * g_dinv[s];
}

// ---------------- tensor-core GEMM (3xTF32): [M,128] @ [128,128] -> [M,128] ----
// R3 version (best measured): double-buffered static smem, re-split in inner loop.
#define TF32_MASK 0xFFFFE000u

__device__ __forceinline__ void mma_tf32(float* c, const unsigned* a,
                                         unsigned b0, unsigned b1) {
    asm volatile(
        "mma.sync.aligned.m16n8k8.row.col.f32.tf32.tf32.f32 "
        "{%0,%1,%2,%3}, {%4,%5,%6,%7}, {%8,%9}, {%0,%1,%2,%3};\n"
        : "+f"(c[0]), "+f"(c[1]), "+f"(c[2]), "+f"(c[3])
        : "r"(a[0]), "r"(a[1]), "r"(a[2]), "r"(a[3]), "r"(b0), "r"(b1));
}

__global__ __launch_bounds__(256, 2)
void sgemm128_tf32(const float* __restrict__ A, const float* __restrict__ B,
                   float* __restrict__ C, int M) {
    __shared__ float As[2][128][20];
    __shared__ float Bs[2][16][136];

    int tid  = threadIdx.x;
    int warp = tid >> 5;
    int lane = tid & 31;
    int g = lane >> 2;      // 0..7
    int t = lane & 3;       // 0..3
    int r0 = warp * 16;
    int rowBase = blockIdx.x * 128;

    int aRow = tid >> 1;          // 0..127
    int aOff = (tid & 1) * 8;     // 0 or 8
    int bRow = tid >> 4;          // 0..15
    int bOff = (tid & 15) * 8;    // 0..120

    bool aOk = (rowBase + aRow) < M;
    const float* Ap = A + (size_t)(aOk ? rowBase + aRow : 0) * 128;

    float acc[16][4];
#pragma unroll
    for (int j = 0; j < 16; j++)
#pragma unroll
        for (int q = 0; q < 4; q++) acc[j][q] = 0.0f;

    // preload stage 0
    {
        float4 z = make_float4(0.f, 0.f, 0.f, 0.f);
        float4 a0 = aOk ? *(const float4*)(Ap + aOff)     : z;
        float4 a1 = aOk ? *(const float4*)(Ap + aOff + 4) : z;
        *(float4*)&As[0][aRow][aOff]     = a0;
        *(float4*)&As[0][aRow][aOff + 4] = a1;
        float4 b0 = *(const float4*)(B + (size_t)bRow * 128 + bOff);
        float4 b1 = *(const float4*)(B + (size_t)bRow * 128 + bOff + 4);
        *(float4*)&Bs[0][bRow][bOff]     = b0;
        *(float4*)&Bs[0][bRow][bOff + 4] = b1;
    }
    __syncthreads();

    int p = 0;
    for (int k0 = 0; k0 < 128; k0 += 16) {
        bool more = (k0 + 16) < 128;
        float4 pa0, pa1, pb0, pb1;
        if (more) {
            float4 z = make_float4(0.f, 0.f, 0.f, 0.f);
            pa0 = aOk ? *(const float4*)(Ap + k0 + 16 + aOff)     : z;
            pa1 = aOk ? *(const float4*)(Ap + k0 + 16 + aOff + 4) : z;
            pb0 = *(const float4*)(B + (size_t)(k0 + 16 + bRow) * 128 + bOff);
            pb1 = *(const float4*)(B + (size_t)(k0 + 16 + bRow) * 128 + bOff + 4);
        }

#pragma unroll
        for (int kk = 0; kk < 16; kk += 8) {
            float av0 = As[p][r0 + g    ][kk + t];
            float av1 = As[p][r0 + g + 8][kk + t];
            float av2 = As[p][r0 + g    ][kk + t + 4];
            float av3 = As[p][r0 + g + 8][kk + t + 4];
            unsigned ahi[4], alo[4];
            {
                float av[4] = {av0, av1, av2, av3};
#pragma unroll
                for (int q = 0; q < 4; q++) {
                    unsigned h = __float_as_uint(av[q]) & TF32_MASK;
                    ahi[q] = h;
                    alo[q] = __float_as_uint(av[q] - __uint_as_float(h));
                }
            }
#pragma unroll
            for (int j = 0; j < 16; j++) {
                float bv0 = Bs[p][kk + t    ][j * 8 + g];
                float bv1 = Bs[p][kk + t + 4][j * 8 + g];
                unsigned bh0 = __float_as_uint(bv0) & TF32_MASK;
                unsigned bh1 = __float_as_uint(bv1) & TF32_MASK;
                unsigned bl0 = __float_as_uint(bv0 - __uint_as_float(bh0));
                unsigned bl1 = __float_as_uint(bv1 - __uint_as_float(bh1));
                mma_tf32(acc[j], ahi, bh0, bh1);   // hi*hi
                mma_tf32(acc[j], ahi, bl0, bl1);   // hi*lo
                mma_tf32(acc[j], alo, bh0, bh1);   // lo*hi
            }
        }

        if (more) {
            int q = p ^ 1;
            *(float4*)&As[q][aRow][aOff]     = pa0;
            *(float4*)&As[q][aRow][aOff + 4] = pa1;
            *(float4*)&Bs[q][bRow][bOff]     = pb0;
            *(float4*)&Bs[q][bRow][bOff + 4] = pb1;
            __syncthreads();
            p = q;
        }
    }

    int rA = rowBase + r0 + g;
    int rB = rA + 8;
#pragma unroll
    for (int j = 0; j < 16; j++) {
        int col = j * 8 + 2 * t;
        if (rA < M) *(float2*)(C + (size_t)rA * 128 + col) = make_float2(acc[j][0], acc[j][1]);
        if (rB < M) *(float2*)(C + (size_t)rB * 128 + col) = make_float2(acc[j][2], acc[j][3]);
    }
}

// ---------------- aggregation ----------------
__global__ __launch_bounds__(256)
void agg_h128(const float* __restrict__ h, float* __restrict__ out,
              const float* __restrict__ bias, int do_relu, int n) {
    int gw = (blockIdx.x * blockDim.x + threadIdx.x) >> 5;
    if (gw >= n) return;
    int lane = threadIdx.x & 31;
    const float4* h4 = (const float4*)h;

    float di = g_dinv[gw];
    float4 acc = h4[gw * 32 + lane];
    acc.x *= di; acc.y *= di; acc.z *= di; acc.w *= di;

    int j = g_row[gw];
    int end = g_row[gw + 1];
    for (; j + 4 <= end; j += 4) {
        int s0 = g_esrc[j], s1 = g_esrc[j + 1], s2 = g_esrc[j + 2], s3 = g_esrc[j + 3];
        float w0 = g_ew2[j], w1 = g_ew2[j + 1], w2 = g_ew2[j + 2], w3 = g_ew2[j + 3];
        float4 v0 = h4[s0 * 32 + lane];
        float4 v1 = h4[s1 * 32 + lane];
        float4 v2 = h4[s2 * 32 + lane];
        float4 v3 = h4[s3 * 32 + lane];
        acc.x = fmaf(w0, v0.x, acc.x); acc.y = fmaf(w0, v0.y, acc.y);
        acc.z = fmaf(w0, v0.z, acc.z); acc.w = fmaf(w0, v0.w, acc.w);
        acc.x = fmaf(w1, v1.x, acc.x); acc.y = fmaf(w1, v1.y, acc.y);
        acc.z = fmaf(w1, v1.z, acc.z); acc.w = fmaf(w1, v1.w, acc.w);
        acc.x = fmaf(w2, v2.x, acc.x); acc.y = fmaf(w2, v2.y, acc.y);
        acc.z = fmaf(w2, v2.z, acc.z); acc.w = fmaf(w2, v2.w, acc.w);
        acc.x = fmaf(w3, v3.x, acc.x); acc.y = fmaf(w3, v3.y, acc.y);
        acc.z = fmaf(w3, v3.z, acc.z); acc.w = fmaf(w3, v3.w, acc.w);
    }
    for (; j < end; j++) {
        int s = g_esrc[j];
        float w = g_ew2[j];
        float4 v = h4[s * 32 + lane];
        acc.x = fmaf(w, v.x, acc.x); acc.y = fmaf(w, v.y, acc.y);
        acc.z = fmaf(w, v.z, acc.z); acc.w = fmaf(w, v.w, acc.w);
    }

    float4 bb = ((const float4*)bias)[lane];
    acc.x = fmaf(acc.x, di, bb.x);
    acc.y = fmaf(acc.y, di, bb.y);
    acc.z = fmaf(acc.z, di, bb.z);
    acc.w = fmaf(acc.w, di, bb.w);
    if (do_relu) {
        acc.x = fmaxf(acc.x, 0.f); acc.y = fmaxf(acc.y, 0.f);
        acc.z = fmaxf(acc.z, 0.f); acc.w = fmaxf(acc.w, 0.f);
    }
    ((float4*)out)[gw * 32 + lane] = acc;
}

// ---------------- layer 3 projection ----------------
__global__ __launch_bounds__(512)
void gemm_w3(const float* __restrict__ A, const float* __restrict__ W, int M) {
    __shared__ float xs[32][128];
    __shared__ float Ws[128 * CCNT];
    int tid = threadIdx.x;
    int r0 = blockIdx.x * 32;

    for (int t = tid; t < 1024; t += 512) {
        int r = t >> 5;
        int c4 = (t & 31) << 2;
        int grow = r0 + r;
        float4 v = make_float4(0.f, 0.f, 0.f, 0.f);
        if (grow < M) v = *(const float4*)(A + (size_t)grow * 128 + c4);
        *(float4*)&xs[r][c4] = v;
    }
    for (int t = tid; t < 128 * CCNT; t += 512) Ws[t] = W[t];
    __syncthreads();

    int r = tid >> 4;
    int c = tid & 15;
    if (c < CCNT) {
        float acc = 0.0f;
#pragma unroll
        for (int k = 0; k < 128; k++)
            acc = fmaf(xs[r][k], Ws[k * CCNT + c], acc);
        int grow = r0 + r;
        if (grow < M) g_h3[grow * 16 + c] = acc;
    }
}

// ---------------- layer 3 aggregation + pool ----------------
__global__ __launch_bounds__(256)
void agg_c16_pool(const int* __restrict__ batch, const float* __restrict__ b3, int n) {
    int gw = (blockIdx.x * blockDim.x + threadIdx.x) >> 5;
    if (gw >= n) return;
    int lane = threadIdx.x & 31;
    bool active = (lane < CCNT);

    float di = g_dinv[gw];
    float acc = 0.0f;
    if (active) acc = g_h3[gw * 16 + lane] * di;

    int j = g_row[gw];
    int end = g_row[gw + 1];
    for (; j + 4 <= end; j += 4) {
        int s0 = g_esrc[j], s1 = g_esrc[j + 1], s2 = g_esrc[j + 2], s3 = g_esrc[j + 3];
        float w0 = g_ew2[j], w1 = g_ew2[j + 1], w2 = g_ew2[j + 2], w3 = g_ew2[j + 3];
        if (active) {
            acc = fmaf(w0, g_h3[s0 * 16 + lane], acc);
            acc = fmaf(w1, g_h3[s1 * 16 + lane], acc);
            acc = fmaf(w2, g_h3[s2 * 16 + lane], acc);
            acc = fmaf(w3, g_h3[s3 * 16 + lane], acc);
        }
    }
    for (; j < end; j++) {
        int s = g_esrc[j];
        float w = g_ew2[j];
        if (active) acc = fmaf(w, g_h3[s * 16 + lane], acc);
    }

    int g = batch[gw];
    if (active) {
        acc = fmaf(acc, di, b3[lane]);
        atomicAdd(&g_psum[g * CCNT + lane], acc);
    }
    if (lane == 0) atomicAdd(&g_pcnt[g], 1.0f);
}

// ---------------- final: mean + log_softmax ----------------
__global__ void k_finalize(float* __restrict__ out) {
    int g = threadIdx.x;
    if (g >= GCNT) return;
    float c = fmaxf(g_pcnt[g], 1.0f);
    float v[CCNT];
    float m = -1e30f;
#pragma unroll
    for (int j = 0; j < CCNT; j++) {
        v[j] = g_psum[g * CCNT + j] / c;
        m = fmaxf(m, v[j]);
    }
    float s = 0.0f;
#pragma unroll
    for (int j = 0; j < CCNT; j++) s += expf(v[j] - m);
    float lse = logf(s) + m;
#pragma unroll
    for (int j = 0; j < CCNT; j++) out[g * CCNT + j] = v[j] - lse;
}

// ---------------- launch ----------------
extern "C" void kernel_launch(void* const* d_in, const int* in_sizes, int n_in,
                              void* d_out, int out_size) {
    const float* x    = (const float*)d_in[0];
    const int*   ei   = (const int*)d_in[1];
    const float* ea   = (const float*)d_in[2];
    const int*   bat  = (const int*)d_in[3];
    const float* W1   = (const float*)d_in[4];
    const float* b1   = (const float*)d_in[5];
    const float* W2   = (const float*)d_in[6];
    const float* b2   = (const float*)d_in[7];
    const float* W3   = (const float*)d_in[8];
    const float* b3   = (const float*)d_in[9];
    float* out = (float*)d_out;

    int n = in_sizes[0] / HDIM;   // 50000
    int e = in_sizes[1] / 2;      // 800000
    const int* src = ei;
    const int* dst = ei + e;

    float *gh, *gagg;
    cudaGetSymbolAddress((void**)&gh, g_h);
    cudaGetSymbolAddress((void**)&gagg, g_agg);

    int nb = (n + SCAN_BLK - 1) / SCAN_BLK;
    int gemmBlocks = (n + 127) / 128;
    int aggBlocks = (n * 32 + 255) / 256;

    cudaStream_t s0 = (cudaStream_t)0;

    // fork a side stream: layer-1 GEMM is independent of CSR preprocessing
    cudaStream_t s2;
    cudaStreamCreateWithFlags(&s2, cudaStreamNonBlocking);
    cudaEvent_t evFork, evJoin;
    cudaEventCreateWithFlags(&evFork, cudaEventDisableTiming);
    cudaEventCreateWithFlags(&evJoin, cudaEventDisableTiming);

    cudaEventRecord(evFork, s0);
    cudaStreamWaitEvent(s2, evFork, 0);
    sgemm128_tf32<<<gemmBlocks, 256, 0, s2>>>(x, W1, gh, n);   // h = x@W1
    cudaEventRecord(evJoin, s2);

    // preprocessing on main stream (concurrent with the GEMM above)
    k_init<<<(n + 255) / 256, 256, 0, s0>>>(n);
    k_count<<<(e + 255) / 256, 256, 0, s0>>>(dst, ea, e);
    k_scan1<<<nb, SCAN_BLK, 0, s0>>>(n);
    k_scan2<<<1, 128, 0, s0>>>(nb, n, e);
    k_scan3<<<nb, SCAN_BLK, 0, s0>>>(n);
    k_scatter<<<(e + 255) / 256, 256, 0, s0>>>(src, dst, ea, e);

    // join: aggregation needs both CSR and h
    cudaStreamWaitEvent(s0, evJoin, 0);
    agg_h128<<<aggBlocks, 256, 0, s0>>>(gh, gagg, b1, 1, n);

    // layer 2
    sgemm128_tf32<<<gemmBlocks, 256, 0, s0>>>(gagg, W2, gh, n);
    agg_h128<<<aggBlocks, 256, 0, s0>>>(gh, gagg, b2, 1, n);

    // layer 3: project to C first, then aggregate + pool
    gemm_w3<<<(n + 31) / 32, 512, 0, s0>>>(gagg, W3, n);
    agg_c16_pool<<<aggBlocks, 256, 0, s0>>>(bat, b3, n);

    k_finalize<<<1, 128, 0, s0>>>(out);
    // NOTE: s2/events intentionally not destroyed — kernel_launch is invoked
    // only for the correctness run and one graph capture.
}